// round 2
// baseline (speedup 1.0000x reference)
#include <cuda_runtime.h>
#include <math.h>

#define BATCH 8
#define NNODE 20000
#define FEATD 256
#define HDIM  512
#define HCW   4096          // B*H
#define F1D   1024
#define KO1   32
#define KO2   10
#define EPSBN 1e-5f

// ---------------- scratch (static device globals; no allocation) ----------------
__device__ float  g_h1[(size_t)BATCH * NNODE * HDIM];   // 327 MB
__device__ float  g_hc[(size_t)NNODE * HCW];            // 327 MB
__device__ float  g_f [(size_t)NNODE * F1D];            // 82 MB
__device__ float  g_f2[(size_t)NNODE * KO1];
__device__ double g_sum1[HCW], g_sq1[HCW];
__device__ float  g_scale1[HCW], g_shift1[HCW];
__device__ double g_sum2[HCW], g_sq2[HCW];
__device__ float  g_scale2[HCW], g_shift2[HCW];

// ---------------- generic tiled SGEMM with fused per-k affine+relu on A ----------------
// C[M x N] = epi( transformA(A[M x K]) * B[K x N] + bias[N] )
// transformA: a' = relu(scale[k]*a + shift[k]) when tScale != nullptr
#define BM 128
#define BN 64
#define BK 16

__global__ void __launch_bounds__(256)
sgemm_kernel(const float* __restrict__ A, long aBatch, int lda,
             const float* __restrict__ B, long bBatch, int ldb,
             const float* __restrict__ bias, int biasBatch,
             float* __restrict__ C, long cBatch, int ldc,
             const float* __restrict__ tScale, const float* __restrict__ tShift, int tBatch,
             int M, int N, int K, int reluEpi)
{
    __shared__ float As[BK][BM + 4];
    __shared__ float Bs[BK][BN];

    const int bz = blockIdx.z;
    A += (long)bz * aBatch;
    B += (long)bz * bBatch;
    C += (long)bz * cBatch;
    const float* biasp = bias + (long)bz * biasBatch;
    const float* tS = tScale ? tScale + (long)bz * tBatch : nullptr;
    const float* tH = tShift ? tShift + (long)bz * tBatch : nullptr;

    const int m0 = blockIdx.x * BM;
    const int n0 = blockIdx.y * BN;
    const int t  = threadIdx.x;
    const int tx = t & 15;        // 16 in n-dir
    const int ty = t >> 4;        // 16 in m-dir

    float acc[8][4];
#pragma unroll
    for (int i = 0; i < 8; i++)
#pragma unroll
        for (int j = 0; j < 4; j++) acc[i][j] = 0.f;

    const int ak = t & 15;        // k within tile for A load
    const int ar = t >> 4;        // base row for A load
    const int bn = t & 63;        // n for B load
    const int bk = t >> 6;        // base k for B load

    for (int k0 = 0; k0 < K; k0 += BK) {
        // A tile: 128 rows x 16 k
        float tsv = 0.f, thv = 0.f;
        if (tS) { tsv = tS[k0 + ak]; thv = tH[k0 + ak]; }
#pragma unroll
        for (int p = 0; p < 8; p++) {
            int r  = ar + p * 16;
            int gm = m0 + r;
            float v = 0.f;
            if (gm < M) v = __ldg(&A[(long)gm * lda + k0 + ak]);
            if (tS) v = fmaxf(fmaf(v, tsv, thv), 0.f);
            As[ak][r] = v;
        }
        // B tile: 16 k x 64 n
#pragma unroll
        for (int p = 0; p < 4; p++) {
            int kk = bk + p * 4;
            Bs[kk][bn] = __ldg(&B[(long)(k0 + kk) * ldb + n0 + bn]);
        }
        __syncthreads();
#pragma unroll
        for (int kk = 0; kk < BK; kk++) {
            float a[8], bb[4];
#pragma unroll
            for (int i = 0; i < 8; i++) a[i] = As[kk][ty * 8 + i];
#pragma unroll
            for (int j = 0; j < 4; j++) bb[j] = Bs[kk][tx * 4 + j];
#pragma unroll
            for (int i = 0; i < 8; i++)
#pragma unroll
                for (int j = 0; j < 4; j++)
                    acc[i][j] = fmaf(a[i], bb[j], acc[i][j]);
        }
        __syncthreads();
    }

#pragma unroll
    for (int i = 0; i < 8; i++) {
        int gm = m0 + ty * 8 + i;
        if (gm >= M) continue;
#pragma unroll
        for (int j = 0; j < 4; j++) {
            int gn = n0 + tx * 4 + j;
            float v = acc[i][j] + biasp[gn];
            if (reluEpi) v = fmaxf(v, 0.f);
            C[(long)gm * ldc + gn] = v;
        }
    }
}

// ---------------- BN statistics ----------------
__global__ void zero_stats_kernel(double* a, double* b, int n)
{
    int i = blockIdx.x * blockDim.x + threadIdx.x;
    if (i < n) { a[i] = 0.0; b[i] = 0.0; }
}

__global__ void stats_kernel(const float* __restrict__ X, long xBatch, int ld, int M,
                             double* __restrict__ sum, double* __restrict__ sq,
                             int sBatch, int rowsPer)
{
    const int col = blockIdx.y * 256 + threadIdx.x;
    const float* Xb = X + (long)blockIdx.z * xBatch;
    int r0 = blockIdx.x * rowsPer;
    int r1 = min(r0 + rowsPer, M);
    double s = 0.0, q = 0.0;
    for (int r = r0; r < r1; r++) {
        float v = __ldg(&Xb[(long)r * ld + col]);
        s += v;
        q += (double)v * (double)v;
    }
    atomicAdd(&sum[blockIdx.z * sBatch + col], s);
    atomicAdd(&sq [blockIdx.z * sBatch + col], q);
}

__global__ void finalize_bn_kernel(const double* __restrict__ sum, const double* __restrict__ sq,
                                   const float* __restrict__ g, const float* __restrict__ be,
                                   float* __restrict__ sc, float* __restrict__ sh,
                                   int n, float invN)
{
    int i = blockIdx.x * blockDim.x + threadIdx.x;
    if (i >= n) return;
    float mu  = (float)(sum[i] * (double)invN);
    float var = (float)(sq[i] * (double)invN) - mu * mu;
    float s = g[i] * rsqrtf(var + EPSBN);
    sc[i] = s;
    sh[i] = be[i] - mu * s;
}

// ---------------- KAN ----------------
// Uniform grid: g[j] = (j-3)*0.4 - 1, j = 0..11 ; spline order 3 -> 8 final bases
__device__ __forceinline__ void bspline8(float x, float bs[11])
{
#pragma unroll
    for (int j = 0; j < 11; j++) {
        float gl = (float)(j - 3) * 0.4f - 1.0f;
        float gr = (float)(j - 2) * 0.4f - 1.0f;
        bs[j] = (x >= gl && x < gr) ? 1.0f : 0.0f;
    }
#pragma unroll
    for (int p = 1; p <= 3; p++) {
        float inv = 1.0f / (0.4f * (float)p);
#pragma unroll
        for (int j = 0; j < 11 - p; j++) {
            float gj   = (float)(j - 3) * 0.4f - 1.0f;       // g[j]
            float gjp1 = (float)(j + p - 2) * 0.4f - 1.0f;   // g[j+p+1]
            bs[j] = ((x - gj) * bs[j] + (gjp1 - x) * bs[j + 1]) * inv;
        }
    }
}

template <int IN, int OUTC>
__global__ void __launch_bounds__(128)
kan_kernel(const float* __restrict__ X, const float* __restrict__ bw,
           const float* __restrict__ sw, const float* __restrict__ sc,
           float* __restrict__ out, int n)
{
    int node = blockIdx.x * blockDim.x + threadIdx.x;
    if (node >= n) return;
    float acc[OUTC];
#pragma unroll
    for (int o = 0; o < OUTC; o++) acc[o] = 0.f;

    for (int i = 0; i < IN; i++) {
        float x = __ldg(&X[(long)node * IN + i]);
        float bs[11];
        bspline8(x, bs);
        float s = x / (1.0f + expf(-x));   // silu
#pragma unroll 4
        for (int o = 0; o < OUTC; o++) {
            const float4* swp = (const float4*)(sw + ((long)o * IN + i) * 8);
            float4 w0 = __ldg(&swp[0]);
            float4 w1 = __ldg(&swp[1]);
            float sp = bs[0] * w0.x + bs[1] * w0.y + bs[2] * w0.z + bs[3] * w0.w
                     + bs[4] * w1.x + bs[5] * w1.y + bs[6] * w1.z + bs[7] * w1.w;
            acc[o] = fmaf(s, __ldg(&bw[(long)o * IN + i]),
                     fmaf(sp, __ldg(&sc[(long)o * IN + i]), acc[o]));
        }
    }
#pragma unroll
    for (int o = 0; o < OUTC; o++) out[(long)node * OUTC + o] = acc[o];
}

// ---------------- launch ----------------
extern "C" void kernel_launch(void* const* d_in, const int* in_sizes, int n_in,
                              void* d_out, int out_size)
{
    const float* x   = (const float*)d_in[0];
    // d_in[1] edge_index, d_in[2] edge_attr : unused (ChebConv K=1)
    const float* W1  = (const float*)d_in[3];
    const float* b1  = (const float*)d_in[4];
    const float* gm1 = (const float*)d_in[5];
    const float* bt1 = (const float*)d_in[6];
    const float* W2  = (const float*)d_in[7];
    const float* b2  = (const float*)d_in[8];
    const float* gm2 = (const float*)d_in[9];
    const float* bt2 = (const float*)d_in[10];
    const float* Wf  = (const float*)d_in[11];
    const float* bf  = (const float*)d_in[12];
    const float* bw1 = (const float*)d_in[13];
    const float* sw1 = (const float*)d_in[14];
    const float* sc1 = (const float*)d_in[15];
    const float* bw2 = (const float*)d_in[16];
    const float* sw2 = (const float*)d_in[17];
    const float* sc2 = (const float*)d_in[18];

    float  *h1, *hc, *f, *f2;
    double *s1, *q1, *s2, *q2;
    float  *sca1, *shf1, *sca2, *shf2;
    cudaGetSymbolAddress((void**)&h1,  g_h1);
    cudaGetSymbolAddress((void**)&hc,  g_hc);
    cudaGetSymbolAddress((void**)&f,   g_f);
    cudaGetSymbolAddress((void**)&f2,  g_f2);
    cudaGetSymbolAddress((void**)&s1,  g_sum1);
    cudaGetSymbolAddress((void**)&q1,  g_sq1);
    cudaGetSymbolAddress((void**)&s2,  g_sum2);
    cudaGetSymbolAddress((void**)&q2,  g_sq2);
    cudaGetSymbolAddress((void**)&sca1, g_scale1);
    cudaGetSymbolAddress((void**)&shf1, g_shift1);
    cudaGetSymbolAddress((void**)&sca2, g_scale2);
    cudaGetSymbolAddress((void**)&shf2, g_shift2);

    const int mBlocks = (NNODE + BM - 1) / BM;   // 157

    // 1) h1 = x @ W1 + b1   (per-branch)
    {
        dim3 grid(mBlocks, HDIM / BN, BATCH);
        sgemm_kernel<<<grid, 256>>>(x, (long)NNODE * FEATD, FEATD,
                                    W1, (long)FEATD * HDIM, HDIM,
                                    b1, HDIM,
                                    h1, (long)NNODE * HDIM, HDIM,
                                    nullptr, nullptr, 0,
                                    NNODE, HDIM, FEATD, 0);
    }

    // 2) BN1 stats -> scale/shift (per branch*channel)
    zero_stats_kernel<<<(HCW + 255) / 256, 256>>>(s1, q1, HCW);
    {
        dim3 grid((NNODE + 255) / 256, HDIM / 256, BATCH);
        stats_kernel<<<grid, 256>>>(h1, (long)NNODE * HDIM, HDIM, NNODE, s1, q1, HDIM, 256);
    }
    finalize_bn_kernel<<<(HCW + 255) / 256, 256>>>(s1, q1, gm1, bt1, sca1, shf1, HCW, 1.0f / NNODE);

    // 3) hc[:, b*512:(b+1)*512] = relu(BN1(h1_b)) @ W2_b + b2_b
    {
        dim3 grid(mBlocks, HDIM / BN, BATCH);
        sgemm_kernel<<<grid, 256>>>(h1, (long)NNODE * HDIM, HDIM,
                                    W2, (long)HDIM * HDIM, HDIM,
                                    b2, HDIM,
                                    hc, (long)HDIM /*column offset b*512*/, HCW,
                                    sca1, shf1, HDIM,
                                    NNODE, HDIM, HDIM, 0);
    }

    // 4) BN2 stats over hc columns
    zero_stats_kernel<<<(HCW + 255) / 256, 256>>>(s2, q2, HCW);
    {
        dim3 grid((NNODE + 255) / 256, HCW / 256, 1);
        stats_kernel<<<grid, 256>>>(hc, 0, HCW, NNODE, s2, q2, 0, 256);
    }
    finalize_bn_kernel<<<(HCW + 255) / 256, 256>>>(s2, q2, gm2, bt2, sca2, shf2, HCW, 1.0f / NNODE);

    // 5) f = relu( relu(BN2(hc)) @ Wf + bf )
    {
        dim3 grid(mBlocks, F1D / BN, 1);
        sgemm_kernel<<<grid, 256>>>(hc, 0, HCW,
                                    Wf, 0, F1D,
                                    bf, 0,
                                    f, 0, F1D,
                                    sca2, shf2, 0,
                                    NNODE, F1D, HCW, 1);
    }

    // 6) KAN 1024 -> 32
    kan_kernel<F1D, KO1><<<(NNODE + 127) / 128, 128>>>(f, bw1, sw1, sc1, f2, NNODE);

    // 7) KAN 32 -> 10 -> d_out
    kan_kernel<KO1, KO2><<<(NNODE + 127) / 128, 128>>>(f2, bw2, sw2, sc2, (float*)d_out, NNODE);
}